// round 10
// baseline (speedup 1.0000x reference)
#include <cuda_runtime.h>
#include <cuda_pipeline.h>
#include <math.h>

// Dihedral angle over 4 carbon atoms (indices 0,4,7,11 of 14) for B molecules.
// x: [B, 42] float32, out: [B] float32.
//
// R10: traffic reduction. Instead of streaming full 168B rows (5.25
// sectors/row), gather only the 8x8B chunks covering the 4 carbon positions
// (4.5 sectors/row touched -> ~14% less DRAM read traffic). 8B cp.async into
// a compact 72B/row smem tile, double-buffered persistent pipeline (proven
// structure from R7). 9.2KB smem/CTA -> 16 CTAs/SM.

constexpr int TILE           = 64;     // rows per tile
constexpr int THREADS        = 64;
constexpr int FLOATS_PER_ROW = 42;     // 14 atoms * 3
constexpr int CSTRIDE        = 18;     // compact floats/row (16 data + 2 pad, 72B)
constexpr int CTAS_PER_SM    = 16;

// 8B chunks per row covering atoms 0,4,7,11 (float offsets 0,12,21,33):
// chunk s copies floats [off[s], off[s]+2) -> compact [2s, 2s+2)
__device__ __constant__ int kOff[8] = {0, 2, 12, 14, 20, 22, 32, 34};
// compact layout: idx 0..15 = f0,f1,f2,f3, f12,f13,f14,f15, f20,f21,f22,f23, f32,f33,f34,f35
//   c0 = idx 0,1,2   c1 = idx 4,5,6   c2 = idx 9,10,11   c3 = idx 13,14,15

__global__ __launch_bounds__(THREADS, CTAS_PER_SM)
void dihedral_kernel(const float* __restrict__ x,
                     float* __restrict__ out,
                     int B, int nTiles)
{
    __shared__ float sbuf[2][TILE * CSTRIDE];   // 2 * 4608 B = 9216 B

    const int tid = threadIdx.x;
    const int r0  = tid >> 3;        // fixed row phase for this thread
    const int s   = tid & 7;         // fixed chunk slot for this thread
    const int off = kOff[s];         // source float offset of this slot

    auto issue_tile = [&](int tile, int buf) {
        if (tile < nTiles) {
            const int rows = min(TILE, B - tile * TILE);
            const float* __restrict__ base = x + (size_t)tile * TILE * FLOATS_PER_ROW;
            float* dstbase = sbuf[buf];
            // 8 iterations: thread handles slot s of rows r0, r0+8, ..., r0+56
            #pragma unroll
            for (int i = 0; i < 8; i++) {
                int r = r0 + 8 * i;
                if (r < rows)
                    __pipeline_memcpy_async(&dstbase[r * CSTRIDE + 2 * s],
                                            &base[r * FLOATS_PER_ROW + off], 8);
            }
        }
        __pipeline_commit();   // uniform group counting (possibly empty)
    };

    int tile = blockIdx.x;
    int buf  = 0;

    issue_tile(tile, buf);                       // prologue

    for (; tile < nTiles; tile += gridDim.x) {
        issue_tile(tile + gridDim.x, buf ^ 1);   // prefetch next

        __pipeline_wait_prior(1);                // current tile landed
        __syncthreads();

        const int rows = min(TILE, B - tile * TILE);
        if (tid < rows) {
            const float* cr = sbuf[buf] + tid * CSTRIDE;

            float c0x = cr[0],  c0y = cr[1],  c0z = cr[2];
            float c1x = cr[4],  c1y = cr[5],  c1z = cr[6];
            float c2x = cr[9],  c2y = cr[10], c2z = cr[11];
            float c3x = cr[13], c3y = cr[14], c3z = cr[15];

            float v0x = c1x - c0x, v0y = c1y - c0y, v0z = c1z - c0z;
            float v1x = c2x - c1x, v1y = c2y - c1y, v1z = c2z - c1z;
            float v2x = c3x - c2x, v2y = c3y - c2y, v2z = c3z - c2z;

            // na = cross(-v0, v1)
            float nax = -(v0y * v1z - v0z * v1y);
            float nay = -(v0z * v1x - v0x * v1z);
            float naz = -(v0x * v1y - v0y * v1x);

            // nb = cross(-v1, v2)
            float nbx = -(v1y * v2z - v1z * v2y);
            float nby = -(v1z * v2x - v1x * v2z);
            float nbz = -(v1x * v2y - v1y * v2x);

            float xx = nax * nbx + nay * nby + naz * nbz;

            // xp = cross(na, nb)
            float xpx = nay * nbz - naz * nby;
            float xpy = naz * nbx - nax * nbz;
            float xpz = nax * nby - nay * nbx;

            float inv_n1 = rsqrtf(v1x * v1x + v1y * v1y + v1z * v1z);
            float yy = (v1x * xpx + v1y * xpy + v1z * xpz) * inv_n1;

            out[tile * TILE + tid] = atan2f(yy, xx);
        }
        __syncthreads();   // all reads done before this buffer is refilled
        buf ^= 1;
    }
}

extern "C" void kernel_launch(void* const* d_in, const int* in_sizes, int n_in,
                              void* d_out, int out_size)
{
    // Identify x (the big input) vs mask_matrix (56 elements, constant).
    int xi = 0;
    for (int i = 1; i < n_in; i++)
        if (in_sizes[i] > in_sizes[xi]) xi = i;

    const float* x = (const float*)d_in[xi];
    float* out = (float*)d_out;
    const int B = in_sizes[xi] / FLOATS_PER_ROW;     // 2,000,000
    const int nTiles = (B + TILE - 1) / TILE;        // 31250

    const int grid = 148 * CTAS_PER_SM;              // 2368: one full wave
    dihedral_kernel<<<grid, THREADS>>>(x, out, B, nTiles);
}

// round 12
// speedup vs baseline: 1.3031x; 1.3031x over previous
#include <cuda_runtime.h>
#include <cstdint>
#include <math.h>

// Dihedral angle over 4 carbon atoms (indices 0,4,7,11 of 14) for B molecules.
// x: [B, 42] float32, out: [B] float32.
//
// R11: cp.async.bulk (TMA-class 1D bulk copy) staging with a depth-4
// mbarrier ring. One bulk instruction per 10.75KB tile removes all
// per-element LDGSTS issue, and 3 tiles pending per CTA (x5 CTAs/SM =
// ~161KB in flight/SM) keeps HBM requests flowing during compute.
// Full-row contiguous streaming (R10 showed gathering kills BW).

constexpr int TILE        = 64;                  // rows per tile
constexpr int THREADS     = 64;
constexpr int FPR         = 42;                  // floats per row
constexpr int TILE_FLOATS = TILE * FPR;          // 2688
constexpr int TILE_BYTES  = TILE_FLOATS * 4;     // 10752 (mult of 16)
constexpr int NSTAGES     = 4;                   // power of 2
constexpr int CTAS_PER_SM = 5;

__device__ __forceinline__ uint32_t s2u(const void* p) {
    uint32_t a;
    asm("{ .reg .u64 t; cvta.to.shared.u64 t, %1; cvt.u32.u64 %0, t; }"
        : "=r"(a) : "l"(p));
    return a;
}

__device__ __forceinline__ void mbar_wait(uint32_t mb, int phase) {
    asm volatile(
        "{\n\t"
        ".reg .pred P;\n\t"
        "WL%=:\n\t"
        "mbarrier.try_wait.parity.acquire.cta.shared::cta.b64 P, [%0], %1, 0x989680;\n\t"
        "@P bra WD%=;\n\t"
        "bra WL%=;\n\t"
        "WD%=:\n\t"
        "}"
        :: "r"(mb), "r"(phase) : "memory");
}

__global__ __launch_bounds__(THREADS, CTAS_PER_SM)
void dihedral_kernel(const float* __restrict__ x,
                     float* __restrict__ out,
                     int B, int nTiles)
{
    __shared__ alignas(16) float    sbuf[NSTAGES][TILE_FLOATS];  // 43008 B
    __shared__ alignas(8)  uint64_t mbar[NSTAGES];

    const int tid = threadIdx.x;

    if (tid == 0) {
        #pragma unroll
        for (int s = 0; s < NSTAGES; s++)
            asm volatile("mbarrier.init.shared.b64 [%0], 1;"
                         :: "r"(s2u(&mbar[s])) : "memory");
    }
    __syncthreads();

    // Issue bulk copy of tile (blockIdx.x + k*gridDim.x) into stage k%NSTAGES.
    // Copy size truncated to 16B multiple: the (at most 2) dropped floats are
    // the last row's floats 40,41, which the dihedral never reads.
    auto issue = [&](int k) {
        int t = blockIdx.x + k * (int)gridDim.x;
        if (t >= nTiles) return;
        if (tid == 0) {
            int s     = k & (NSTAGES - 1);
            int rows  = min(TILE, B - t * TILE);
            int bytes = (rows * FPR * 4) & ~15;
            uint32_t mb = s2u(&mbar[s]);
            uint32_t ds = s2u(&sbuf[s][0]);
            const float* src = x + (size_t)t * TILE_FLOATS;   // 16B aligned
            asm volatile("mbarrier.arrive.expect_tx.shared.b64 _, [%0], %1;"
                         :: "r"(mb), "r"(bytes) : "memory");
            asm volatile(
                "cp.async.bulk.shared::cta.global.mbarrier::complete_tx::bytes "
                "[%0], [%1], %2, [%3];"
                :: "r"(ds), "l"(src), "r"(bytes), "r"(mb) : "memory");
        }
    };

    // Prologue: fill NSTAGES-1 stages.
    #pragma unroll
    for (int k = 0; k < NSTAGES - 1; k++) issue(k);

    for (int k = 0;; k++) {
        int t = blockIdx.x + k * (int)gridDim.x;
        if (t >= nTiles) break;

        // Stage (k-1)%N was fully consumed at iteration k-1 (then synced);
        // refill it with tile k+NSTAGES-1.
        issue(k + NSTAGES - 1);

        const int s  = k & (NSTAGES - 1);
        const int ph = (k >> 2) & 1;          // NSTAGES == 4
        mbar_wait(s2u(&mbar[s]), ph);

        const int rows = min(TILE, B - t * TILE);
        if (tid < rows) {
            const float* row = sbuf[s] + tid * FPR;

            // Carbon atoms 0,4,7,11 -> float offsets 0,12,21,33
            float c0x = row[0],  c0y = row[1],  c0z = row[2];
            float c1x = row[12], c1y = row[13], c1z = row[14];
            float c2x = row[21], c2y = row[22], c2z = row[23];
            float c3x = row[33], c3y = row[34], c3z = row[35];

            float v0x = c1x - c0x, v0y = c1y - c0y, v0z = c1z - c0z;
            float v1x = c2x - c1x, v1y = c2y - c1y, v1z = c2z - c1z;
            float v2x = c3x - c2x, v2y = c3y - c2y, v2z = c3z - c2z;

            // na = cross(-v0, v1)
            float nax = -(v0y * v1z - v0z * v1y);
            float nay = -(v0z * v1x - v0x * v1z);
            float naz = -(v0x * v1y - v0y * v1x);

            // nb = cross(-v1, v2)
            float nbx = -(v1y * v2z - v1z * v2y);
            float nby = -(v1z * v2x - v1x * v2z);
            float nbz = -(v1x * v2y - v1y * v2x);

            float xx = nax * nbx + nay * nby + naz * nbz;

            // xp = cross(na, nb)
            float xpx = nay * nbz - naz * nby;
            float xpy = naz * nbx - nax * nbz;
            float xpz = nax * nby - nay * nbx;

            float inv_n1 = rsqrtf(v1x * v1x + v1y * v1y + v1z * v1z);
            float yy = (v1x * xpx + v1y * xpy + v1z * xpz) * inv_n1;

            out[t * TILE + tid] = atan2f(yy, xx);
        }
        __syncthreads();   // all reads done before this stage is refilled
    }
}

extern "C" void kernel_launch(void* const* d_in, const int* in_sizes, int n_in,
                              void* d_out, int out_size)
{
    // Identify x (the big input) vs mask_matrix (56 elements, constant).
    int xi = 0;
    for (int i = 1; i < n_in; i++)
        if (in_sizes[i] > in_sizes[xi]) xi = i;

    const float* x = (const float*)d_in[xi];
    float* out = (float*)d_out;
    const int B = in_sizes[xi] / FPR;                // 2,000,000
    const int nTiles = (B + TILE - 1) / TILE;        // 31250

    const int grid = 148 * CTAS_PER_SM;              // 740: one full wave
    dihedral_kernel<<<grid, THREADS>>>(x, out, B, nTiles);
}